// round 6
// baseline (speedup 1.0000x reference)
#include <cuda_runtime.h>
#include <math.h>

#define N_NODES 20000
#define N_EDGES 100000
#define N_RELS  1000
#define F_DIM   128
#define N_HEAD  4
#define HC      512            // N_HEAD * F_DIM
#define ETOT    (N_EDGES + N_NODES)
#define NEG_SLOPE 0.2f

// ---------------- scratch (device globals; allocation-free) ----------------
__device__ __align__(16) float    g_xl[(size_t)N_NODES * HC];      // 41 MB
__device__ __align__(16) float    g_xr[(size_t)N_NODES * HC];      // 41 MB
__device__ __align__(16) float    g_RE[(N_RELS + 1) * HC];         // 2 MB
__device__ __align__(16) float    g_relext[(N_RELS + 1) * F_DIM];  // 0.5 MB
__device__ __align__(16) float    g_logits[ETOT * N_HEAD];         // 1.9 MB (reused as p)
__device__ __align__(16) unsigned g_menc[N_NODES * N_HEAD];
__device__ __align__(16) float    g_denom[N_NODES * N_HEAD];
__device__ __align__(16) float    g_hA[(size_t)N_NODES * F_DIM];
__device__ __align__(16) float    g_hB[(size_t)N_NODES * F_DIM];
__device__ int g_counts[N_RELS];

// ---------------- helpers ----------------
__device__ __forceinline__ unsigned fenc(float x) {
    unsigned u = __float_as_uint(x);
    return (u & 0x80000000u) ? ~u : (u | 0x80000000u);
}
__device__ __forceinline__ float fdec(unsigned k) {
    return (k & 0x80000000u) ? __uint_as_float(k ^ 0x80000000u) : __uint_as_float(~k);
}
__device__ __forceinline__ float wred(float v) {
    v += __shfl_xor_sync(0xffffffffu, v, 16);
    v += __shfl_xor_sync(0xffffffffu, v, 8);
    v += __shfl_xor_sync(0xffffffffu, v, 4);
    v += __shfl_xor_sync(0xffffffffu, v, 2);
    v += __shfl_xor_sync(0xffffffffu, v, 1);
    return v;
}

// ---------------- small utility kernels ----------------
__global__ void fill_u32(unsigned* p, unsigned v, int n) {
    int i = blockIdx.x * blockDim.x + threadIdx.x;
    if (i < n) p[i] = v;
}

__global__ void count_rels(const int* __restrict__ rel, int* __restrict__ counts) {
    int i = blockIdx.x * blockDim.x + threadIdx.x;
    if (i < N_EDGES) atomicAdd(&counts[rel[i]], 1);
}

// rel_ext[r<1000] = relations[r]; rel_ext[1000] = weighted mean (== ea.mean(axis=0))
__global__ void build_relext(const float* __restrict__ relations,
                             const int* __restrict__ counts,
                             float* __restrict__ relext) {
    int r = blockIdx.x;
    int k = threadIdx.x;   // 128
    if (r < N_RELS) {
        relext[r * F_DIM + k] = relations[r * F_DIM + k];
    } else {
        __shared__ int sc[N_RELS];
        for (int i = k; i < N_RELS; i += 128) sc[i] = counts[i];
        __syncthreads();
        float s = 0.f;
        for (int i = 0; i < N_RELS; i++)
            s = fmaf((float)sc[i], relations[i * F_DIM + k], s);
        relext[r * F_DIM + k] = s * (1.0f / (float)N_EDGES);
    }
}

// ---------------- fp32 GEMM: C[M,512] = A[M,128] @ W[128,512] (+ bias) ----------------
__global__ __launch_bounds__(256) void gemm_k128(const float* __restrict__ A,
                                                 const float* __restrict__ W,
                                                 const float* __restrict__ bias,
                                                 float* __restrict__ C, int M) {
    __shared__ __align__(16) float As[16][64];
    __shared__ __align__(16) float Ws[16][64];
    int tid = threadIdx.x;
    int bm = blockIdx.x * 64;
    int bn = blockIdx.y * 64;
    int tx = tid & 15, ty = tid >> 4;
    float acc[4][4];
#pragma unroll
    for (int i = 0; i < 4; i++)
#pragma unroll
        for (int j = 0; j < 4; j++) acc[i][j] = 0.f;

    int arow = tid >> 2;
    int akq  = (tid & 3) * 4;
    int wkr  = tid >> 4;
    int wnq  = (tid & 15) * 4;
    const bool avalid = (bm + arow) < M;
    const float* aptr = A + (size_t)(bm + arow) * F_DIM + akq;
    const float* wptr = W + (size_t)wkr * HC + bn + wnq;

    for (int k0 = 0; k0 < 128; k0 += 16) {
        float4 av = avalid ? *(const float4*)(aptr + k0) : make_float4(0.f, 0.f, 0.f, 0.f);
        float4 wv = *(const float4*)(wptr + (size_t)k0 * HC);
        As[akq + 0][arow] = av.x; As[akq + 1][arow] = av.y;
        As[akq + 2][arow] = av.z; As[akq + 3][arow] = av.w;
        *(float4*)&Ws[wkr][wnq] = wv;
        __syncthreads();
#pragma unroll
        for (int kk = 0; kk < 16; kk++) {
            float a[4], b[4];
            *(float4*)a = *(const float4*)&As[kk][ty * 4];
            *(float4*)b = *(const float4*)&Ws[kk][tx * 4];
#pragma unroll
            for (int i = 0; i < 4; i++)
#pragma unroll
                for (int j = 0; j < 4; j++)
                    acc[i][j] = fmaf(a[i], b[j], acc[i][j]);
        }
        __syncthreads();
    }
    float bv[4] = {0.f, 0.f, 0.f, 0.f};
    if (bias) *(float4*)bv = *(const float4*)(bias + bn + tx * 4);
#pragma unroll
    for (int i = 0; i < 4; i++) {
        int row = bm + ty * 4 + i;
        if (row < M) {
            float4 o;
            o.x = acc[i][0] + bv[0]; o.y = acc[i][1] + bv[1];
            o.z = acc[i][2] + bv[2]; o.w = acc[i][3] + bv[3];
            *(float4*)(C + (size_t)row * HC + bn + tx * 4) = o;
        }
    }
}

// ---------------- edge scoring: logits + segment max ----------------
__global__ __launch_bounds__(256) void edge_logits(const float* __restrict__ xl,
                                                   const float* __restrict__ xr,
                                                   const float* __restrict__ RE,
                                                   const int* __restrict__ ei,
                                                   const int* __restrict__ rel,
                                                   const float* __restrict__ att,
                                                   float* __restrict__ logits,
                                                   unsigned* __restrict__ menc) {
    int warp = (blockIdx.x * blockDim.x + threadIdx.x) >> 5;
    int lane = threadIdx.x & 31;
    if (warp >= ETOT) return;
    int s, d, r;
    if (warp < N_EDGES) { s = ei[warp]; d = ei[N_EDGES + warp]; r = rel[warp]; }
    else                { s = d = warp - N_EDGES; r = N_RELS; }

    const float4* pl = (const float4*)(xl + (size_t)s * HC);
    const float4* pr = (const float4*)(xr + (size_t)d * HC);
    const float4* pe = (const float4*)(RE + (size_t)r * HC);
    const float4* pa = (const float4*)att;

    float lg[4];
#pragma unroll
    for (int h = 0; h < 4; h++) {
        int idx = h * 32 + lane;
        float4 a = pl[idx], b = pr[idx], c = pe[idx], t = pa[idx];
        float x0 = a.x + b.x + c.x; x0 = x0 > 0.f ? x0 : NEG_SLOPE * x0;
        float x1 = a.y + b.y + c.y; x1 = x1 > 0.f ? x1 : NEG_SLOPE * x1;
        float x2 = a.z + b.z + c.z; x2 = x2 > 0.f ? x2 : NEG_SLOPE * x2;
        float x3 = a.w + b.w + c.w; x3 = x3 > 0.f ? x3 : NEG_SLOPE * x3;
        float sum = fmaf(x0, t.x, fmaf(x1, t.y, fmaf(x2, t.z, x3 * t.w)));
        lg[h] = wred(sum);
    }
    if (lane == 0) {
        *(float4*)(logits + (size_t)warp * 4) = make_float4(lg[0], lg[1], lg[2], lg[3]);
        atomicMax(&menc[d * 4 + 0], fenc(lg[0]));
        atomicMax(&menc[d * 4 + 1], fenc(lg[1]));
        atomicMax(&menc[d * 4 + 2], fenc(lg[2]));
        atomicMax(&menc[d * 4 + 3], fenc(lg[3]));
    }
}

// ---------------- softmax numerator + denominators ----------------
__global__ void softmax_p(float* __restrict__ logits,
                          const unsigned* __restrict__ menc,
                          float* __restrict__ denom,
                          const int* __restrict__ ei) {
    int i = blockIdx.x * blockDim.x + threadIdx.x;
    if (i >= ETOT * N_HEAD) return;
    int e = i >> 2, h = i & 3;
    int d = (e < N_EDGES) ? ei[N_EDGES + e] : (e - N_EDGES);
    float m = fdec(menc[d * 4 + h]);
    float p = expf(logits[i] - m);
    logits[i] = p;
    atomicAdd(&denom[d * 4 + h], p);
}

// ---------------- init out with bias ----------------
__global__ void init_out(float* __restrict__ out, const float* __restrict__ bias) {
    int i = blockIdx.x * blockDim.x + threadIdx.x;
    if (i < N_NODES * F_DIM) out[i] = bias[i & (F_DIM - 1)];
}

// ---------------- aggregation: out[dst] += mean_h alpha_h * xl[src][h,:] ----------------
__global__ __launch_bounds__(256) void aggregate(const float* __restrict__ xl,
                                                 const float* __restrict__ p,
                                                 const float* __restrict__ denom,
                                                 const int* __restrict__ ei,
                                                 float* __restrict__ out) {
    int warp = (blockIdx.x * blockDim.x + threadIdx.x) >> 5;
    int lane = threadIdx.x & 31;
    if (warp >= ETOT) return;
    int s, d;
    if (warp < N_EDGES) { s = ei[warp]; d = ei[N_EDGES + warp]; }
    else                { s = d = warp - N_EDGES; }

    float4 p4 = *(const float4*)(p + (size_t)warp * 4);
    float4 dn = *(const float4*)(denom + (size_t)d * 4);
    float a0 = 0.25f * p4.x / dn.x;
    float a1 = 0.25f * p4.y / dn.y;
    float a2 = 0.25f * p4.z / dn.z;
    float a3 = 0.25f * p4.w / dn.w;

    const float* base = xl + (size_t)s * HC;
    float4 v0 = ((const float4*)(base      ))[lane];
    float4 v1 = ((const float4*)(base + 128))[lane];
    float4 v2 = ((const float4*)(base + 256))[lane];
    float4 v3 = ((const float4*)(base + 384))[lane];

    float4 acc;
    acc.x = fmaf(a0, v0.x, fmaf(a1, v1.x, fmaf(a2, v2.x, a3 * v3.x)));
    acc.y = fmaf(a0, v0.y, fmaf(a1, v1.y, fmaf(a2, v2.y, a3 * v3.y)));
    acc.z = fmaf(a0, v0.z, fmaf(a1, v1.z, fmaf(a2, v2.z, a3 * v3.z)));
    acc.w = fmaf(a0, v0.w, fmaf(a1, v1.w, fmaf(a2, v2.w, a3 * v3.w)));

    float* op = out + (size_t)d * F_DIM + lane * 4;
    atomicAdd(op + 0, acc.x);
    atomicAdd(op + 1, acc.y);
    atomicAdd(op + 2, acc.z);
    atomicAdd(op + 3, acc.w);
}

// ---------------- tail: copy relations into output ----------------
__global__ void copy_rel(const float* __restrict__ relations, float* __restrict__ out) {
    int i = blockIdx.x * blockDim.x + threadIdx.x;
    if (i < N_RELS * F_DIM) out[(size_t)N_NODES * F_DIM + i] = relations[i];
}

// ---------------- host ----------------
extern "C" void kernel_launch(void* const* d_in, const int* in_sizes, int n_in,
                              void* d_out, int out_size) {
    (void)in_sizes; (void)n_in; (void)out_size;
    const float* x         = (const float*)d_in[0];
    const int*   ei        = (const int*)  d_in[1];
    const float* relations = (const float*)d_in[2];
    const int*   relidx    = (const int*)  d_in[3];
    const float* Wl        = (const float*)d_in[4];
    const float* bl        = (const float*)d_in[5];
    const float* Wr        = (const float*)d_in[6];
    const float* br        = (const float*)d_in[7];
    const float* We        = (const float*)d_in[8];
    const float* att       = (const float*)d_in[9];
    const float* bias      = (const float*)d_in[10];
    float* out = (float*)d_out;

    float *xl, *xr, *RE, *relext, *logits, *denom, *hA, *hB;
    unsigned* menc; int* counts;
    cudaGetSymbolAddress((void**)&xl, g_xl);
    cudaGetSymbolAddress((void**)&xr, g_xr);
    cudaGetSymbolAddress((void**)&RE, g_RE);
    cudaGetSymbolAddress((void**)&relext, g_relext);
    cudaGetSymbolAddress((void**)&logits, g_logits);
    cudaGetSymbolAddress((void**)&menc, g_menc);
    cudaGetSymbolAddress((void**)&denom, g_denom);
    cudaGetSymbolAddress((void**)&hA, g_hA);
    cudaGetSymbolAddress((void**)&hB, g_hB);
    cudaGetSymbolAddress((void**)&counts, g_counts);

    // relation mean row (ea.mean) via deterministic integer counts
    fill_u32<<<(N_RELS + 255) / 256, 256>>>((unsigned*)counts, 0u, N_RELS);
    count_rels<<<(N_EDGES + 255) / 256, 256>>>(relidx, counts);
    build_relext<<<N_RELS + 1, 128>>>(relations, counts, relext);

    dim3 gN((N_NODES + 63) / 64, HC / 64);
    dim3 gR((N_RELS + 1 + 63) / 64, HC / 64);
    int edgeBlocks = (ETOT * 32 + 255) / 256;

    const float* cur = x;
    for (int l = 0; l < 4; l++) {
        float* outb = (l == 3) ? out : ((l & 1) ? hB : hA);
        gemm_k128<<<gN, 256>>>(cur, Wl + (size_t)l * F_DIM * HC, bl + l * HC, xl, N_NODES);
        gemm_k128<<<gN, 256>>>(cur, Wr + (size_t)l * F_DIM * HC, br + l * HC, xr, N_NODES);
        gemm_k128<<<gR, 256>>>(relext, We + (size_t)l * F_DIM * HC, (const float*)0, RE, N_RELS + 1);
        fill_u32<<<(N_NODES * N_HEAD + 255) / 256, 256>>>(menc, 0u, N_NODES * N_HEAD);
        fill_u32<<<(N_NODES * N_HEAD + 255) / 256, 256>>>((unsigned*)denom, 0u, N_NODES * N_HEAD);
        edge_logits<<<edgeBlocks, 256>>>(xl, xr, RE, ei, relidx, att + l * N_HEAD * F_DIM,
                                         logits, menc);
        softmax_p<<<(ETOT * N_HEAD + 255) / 256, 256>>>(logits, menc, denom, ei);
        init_out<<<(N_NODES * F_DIM + 255) / 256, 256>>>(outb, bias + l * F_DIM);
        aggregate<<<edgeBlocks, 256>>>(xl, logits, denom, ei, outb);
        cur = outb;
    }
    copy_rel<<<(N_RELS * F_DIM + 255) / 256, 256>>>(relations, out);
}

// round 11
// speedup vs baseline: 1.5392x; 1.5392x over previous
#include <cuda_runtime.h>
#include <cuda_bf16.h>
#include <math.h>
#include <stdint.h>

#define N_NODES 20000
#define N_EDGES 100000
#define N_RELS  1000
#define F_DIM   128
#define N_HEAD  4
#define HC      512            // N_HEAD * F_DIM
#define ETOT    (N_EDGES + N_NODES)
#define NEG_SLOPE 0.2f
#define KTOT    384            // 3-term split contraction length

// ===================== scratch (device globals; allocation-free) ==========
__device__ __align__(16) float    g_xl[(size_t)N_NODES * HC];      // 41 MB
__device__ __align__(16) float    g_xr[(size_t)N_NODES * HC];      // 41 MB
__device__ __align__(16) float    g_RE[(N_RELS + 1) * HC];         // 2 MB
__device__ __align__(16) float    g_relext[(N_RELS + 1) * F_DIM];  // 0.5 MB
__device__ __align__(16) float    g_logits[ETOT * N_HEAD];         // 1.9 MB (reused as p)
__device__ __align__(16) unsigned g_menc[N_NODES * N_HEAD];
__device__ __align__(16) float    g_denom[N_NODES * N_HEAD];
__device__ __align__(16) float    g_hA[(size_t)N_NODES * F_DIM];
__device__ __align__(16) float    g_hB[(size_t)N_NODES * F_DIM];
__device__ int g_counts[N_RELS];
// bf16 3-term split operands: A3[m][384] = [Ah|Al|Ah], W3[l][n][384] = [Wh|Wh|Wl]
__device__ __align__(16) __nv_bfloat16 g_A3[(size_t)N_NODES * KTOT];    // 15.4 MB
__device__ __align__(16) __nv_bfloat16 g_W3[(size_t)4 * 1024 * KTOT];   // 3.1 MB
__device__ __align__(16) float         g_bc[4 * 1024];                  // combined bias

// ===================== generic helpers ====================================
__device__ __forceinline__ unsigned fenc(float x) {
    unsigned u = __float_as_uint(x);
    return (u & 0x80000000u) ? ~u : (u | 0x80000000u);
}
__device__ __forceinline__ float fdec(unsigned k) {
    return (k & 0x80000000u) ? __uint_as_float(k ^ 0x80000000u) : __uint_as_float(~k);
}
__device__ __forceinline__ float wred(float v) {
    v += __shfl_xor_sync(0xffffffffu, v, 16);
    v += __shfl_xor_sync(0xffffffffu, v, 8);
    v += __shfl_xor_sync(0xffffffffu, v, 4);
    v += __shfl_xor_sync(0xffffffffu, v, 2);
    v += __shfl_xor_sync(0xffffffffu, v, 1);
    return v;
}
__device__ __forceinline__ uint32_t smem_u32(const void* p) {
    uint32_t a;
    asm("{ .reg .u64 t; cvta.to.shared.u64 t, %1; cvt.u32.u64 %0, t; }" : "=r"(a) : "l"(p));
    return a;
}
__device__ __forceinline__ uint32_t swz(uint32_t b) { return b ^ ((b >> 3) & 0x70u); }

// ===================== small utility kernels ==============================
__global__ void fill_u32(unsigned* p, unsigned v, int n) {
    int i = blockIdx.x * blockDim.x + threadIdx.x;
    if (i < n) p[i] = v;
}
__global__ void count_rels(const int* __restrict__ rel, int* __restrict__ counts) {
    int i = blockIdx.x * blockDim.x + threadIdx.x;
    if (i < N_EDGES) atomicAdd(&counts[rel[i]], 1);
}
__global__ void build_relext(const float* __restrict__ relations,
                             const int* __restrict__ counts,
                             float* __restrict__ relext) {
    int r = blockIdx.x;
    int k = threadIdx.x;   // 128
    if (r < N_RELS) {
        relext[r * F_DIM + k] = relations[r * F_DIM + k];
    } else {
        __shared__ int sc[N_RELS];
        for (int i = k; i < N_RELS; i += 128) sc[i] = counts[i];
        __syncthreads();
        float s = 0.f;
        for (int i = 0; i < N_RELS; i++)
            s = fmaf((float)sc[i], relations[i * F_DIM + k], s);
        relext[r * F_DIM + k] = s * (1.0f / (float)N_EDGES);
    }
}

// A3[m][0:128]=hi, [128:256]=lo, [256:384]=hi
__global__ void split_A3(const float* __restrict__ in, __nv_bfloat16* __restrict__ A3) {
    int i = blockIdx.x * blockDim.x + threadIdx.x;
    if (i >= N_NODES * F_DIM) return;
    int m = i >> 7, k = i & 127;
    float v = in[i];
    __nv_bfloat16 h = __float2bfloat16(v);
    __nv_bfloat16 l = __float2bfloat16(v - __bfloat162float(h));
    __nv_bfloat16* row = A3 + (size_t)m * KTOT;
    row[k] = h; row[128 + k] = l; row[256 + k] = h;
}

// W3[l][n][0:128]=Wh, [128:256]=Wh, [256:384]=Wl ; n<512 from Wl-proj, else Wr-proj
__global__ void split_W3(const float* __restrict__ Wl, const float* __restrict__ Wr,
                         const float* __restrict__ bl, const float* __restrict__ br,
                         __nv_bfloat16* __restrict__ W3, float* __restrict__ bc) {
    int idx = blockIdx.x * blockDim.x + threadIdx.x;
    if (idx < 4 * 1024) {
        int l = idx >> 10, n = idx & 1023;
        bc[idx] = (n < 512) ? bl[l * 512 + n] : br[l * 512 + (n - 512)];
    }
    if (idx >= 4 * 1024 * F_DIM) return;
    int l = idx / (1024 * F_DIM);
    int rem = idx - l * 1024 * F_DIM;
    int n = rem >> 7, k = rem & 127;
    float v = (n < 512) ? Wl[(size_t)l * F_DIM * 512 + (size_t)k * 512 + n]
                        : Wr[(size_t)l * F_DIM * 512 + (size_t)k * 512 + (n - 512)];
    __nv_bfloat16 h = __float2bfloat16(v);
    __nv_bfloat16 lo = __float2bfloat16(v - __bfloat162float(h));
    __nv_bfloat16* row = W3 + ((size_t)l * 1024 + n) * KTOT;
    row[k] = h; row[128 + k] = h; row[256 + k] = lo;
}

// ===================== mma.sync bf16 GEMM =================================
// C[m, n1024] = A3[m,384] @ W3[n,384]^T ; 128x128 tile, K-chunks of 64, dbuf.
#define BM 128
#define BN 128
#define BK 64
#define NCHUNK 6
#define CHUNK_BYTES 16384        // 128 rows * 128 B
#define BUF_BYTES   32768        // A chunk + B chunk
#define SMEM_MMA    65536        // 2 buffers

__device__ __forceinline__ void ldsm4(uint32_t& r0, uint32_t& r1, uint32_t& r2,
                                      uint32_t& r3, uint32_t addr) {
    asm volatile("ldmatrix.sync.aligned.m8n8.x4.shared.b16 {%0,%1,%2,%3}, [%4];"
                 : "=r"(r0), "=r"(r1), "=r"(r2), "=r"(r3) : "r"(addr));
}
__device__ __forceinline__ void mma16816(float* c, const uint32_t* a, const uint32_t* b) {
    asm volatile(
        "mma.sync.aligned.m16n8k16.row.col.f32.bf16.bf16.f32 "
        "{%0,%1,%2,%3}, {%4,%5,%6,%7}, {%8,%9}, {%0,%1,%2,%3};"
        : "+f"(c[0]), "+f"(c[1]), "+f"(c[2]), "+f"(c[3])
        : "r"(a[0]), "r"(a[1]), "r"(a[2]), "r"(a[3]), "r"(b[0]), "r"(b[1]));
}

__global__ __launch_bounds__(256, 2) void gemm_mma(
    const __nv_bfloat16* __restrict__ A3, const __nv_bfloat16* __restrict__ W3,
    const float* __restrict__ bc,
    float* __restrict__ xl, float* __restrict__ xr, int Mtot) {
    extern __shared__ char smem[];
    uint32_t sb = smem_u32(smem);
    int tid = threadIdx.x;
    int wid = tid >> 5, lane = tid & 31;
    int bm = blockIdx.x * BM;
    int n0 = blockIdx.y * BN;
    int wm = wid & 1;          // 2 m-groups of 64
    int wn = wid >> 1;         // 4 n-groups of 32

    // -------- async chunk loader --------
    auto load_chunk = [&](int buf, int k0) {
        uint32_t abase = sb + buf * BUF_BYTES;
        uint32_t bbase = abase + CHUNK_BYTES;
#pragma unroll
        for (int p = 0; p < 4; p++) {
            int unit = tid + p * 256;              // 0..1023
            int row = unit >> 3, c16 = unit & 7;
            uint32_t off = swz((uint32_t)(row * 128 + c16 * 16));
            const void* asrc = A3 + (size_t)(bm + row) * KTOT + k0 + c16 * 8;
            int sz = (bm + row < Mtot) ? 16 : 0;
            asm volatile("cp.async.cg.shared.global [%0], [%1], 16, %2;"
                         :: "r"(abase + off), "l"(asrc), "r"(sz) : "memory");
            const void* bsrc = W3 + (size_t)(n0 + row) * KTOT + k0 + c16 * 8;
            asm volatile("cp.async.cg.shared.global [%0], [%1], 16;"
                         :: "r"(bbase + off), "l"(bsrc) : "memory");
        }
        asm volatile("cp.async.commit_group;" ::: "memory");
    };

    // lane -> fragment address components (swizzled, buffer-relative)
    uint32_t aSw[4], bSw[2];
#pragma unroll
    for (int mf = 0; mf < 4; mf++) {
        int row = wm * 64 + mf * 16 + (lane & 15);
        aSw[mf] = swz((uint32_t)(row * 128 + ((lane >> 4) << 4)));
    }
#pragma unroll
    for (int nh = 0; nh < 2; nh++) {
        int row = wn * 32 + nh * 16 + (lane & 7) + ((lane & 16) ? 8 : 0);
        bSw[nh] = swz((uint32_t)(row * 128 + ((lane & 8) ? 16 : 0)));
    }

    float acc[4][4][4] = {};

    load_chunk(0, 0);
#pragma unroll
    for (int c = 0; c < NCHUNK; c++) {
        if (c + 1 < NCHUNK) {
            load_chunk((c + 1) & 1, (c + 1) * BK);
            asm volatile("cp.async.wait_group 1;" ::: "memory");
        } else {
            asm volatile("cp.async.wait_group 0;" ::: "memory");
        }
        __syncthreads();
        uint32_t As = sb + (c & 1) * BUF_BYTES;
        uint32_t Bs = As + CHUNK_BYTES;
#pragma unroll
        for (int kk = 0; kk < 4; kk++) {
            uint32_t kx = (uint32_t)kk << 5;
            uint32_t a[4][4], b[4][2];
#pragma unroll
            for (int mf = 0; mf < 4; mf++)
                ldsm4(a[mf][0], a[mf][1], a[mf][2], a[mf][3], As + (aSw[mf] ^ kx));
#pragma unroll
            for (int nh = 0; nh < 2; nh++) {
                uint32_t r0, r1, r2, r3;
                ldsm4(r0, r1, r2, r3, Bs + (bSw[nh] ^ kx));
                b[nh * 2][0] = r0; b[nh * 2][1] = r1;
                b[nh * 2 + 1][0] = r2; b[nh * 2 + 1][1] = r3;
            }
#pragma unroll
            for (int mf = 0; mf < 4; mf++)
#pragma unroll
                for (int nf = 0; nf < 4; nf++)
                    mma16816(acc[mf][nf], a[mf], b[nf]);
        }
        __syncthreads();
    }

    // -------- epilogue: bias + store to xl/xr --------
    float* outp = (n0 < 512) ? xl : xr;
    int col0 = (n0 < 512) ? n0 : n0 - 512;
#pragma unroll
    for (int mf = 0; mf < 4; mf++) {
        int m0 = bm + wm * 64 + mf * 16 + (lane >> 2);
#pragma unroll
        for (int nf = 0; nf < 4; nf++) {
            int cl = wn * 32 + nf * 8 + (lane & 3) * 2;
            float bx = __ldg(bc + n0 + cl), by = __ldg(bc + n0 + cl + 1);
            if (m0 < Mtot) {
                float2 v = make_float2(acc[mf][nf][0] + bx, acc[mf][nf][1] + by);
                *(float2*)(outp + (size_t)m0 * 512 + col0 + cl) = v;
            }
            if (m0 + 8 < Mtot) {
                float2 v = make_float2(acc[mf][nf][2] + bx, acc[mf][nf][3] + by);
                *(float2*)(outp + (size_t)(m0 + 8) * 512 + col0 + cl) = v;
            }
        }
    }
}

// ===================== fp32 GEMM (kept for the small RE matmul) ===========
__global__ __launch_bounds__(256) void gemm_k128(const float* __restrict__ A,
                                                 const float* __restrict__ W,
                                                 const float* __restrict__ bias,
                                                 float* __restrict__ C, int M) {
    __shared__ __align__(16) float As[16][64];
    __shared__ __align__(16) float Ws[16][64];
    int tid = threadIdx.x;
    int bm = blockIdx.x * 64;
    int bn = blockIdx.y * 64;
    int tx = tid & 15, ty = tid >> 4;
    float acc[4][4];
#pragma unroll
    for (int i = 0; i < 4; i++)
#pragma unroll
        for (int j = 0; j < 4; j++) acc[i][j] = 0.f;
    int arow = tid >> 2;
    int akq  = (tid & 3) * 4;
    int wkr  = tid >> 4;
    int wnq  = (tid & 15) * 4;
    const bool avalid = (bm + arow) < M;
    const float* aptr = A + (size_t)(bm + arow) * F_DIM + akq;
    const float* wptr = W + (size_t)wkr * HC + bn + wnq;
    for (int k0 = 0; k0 < 128; k0 += 16) {
        float4 av = avalid ? *(const float4*)(aptr + k0) : make_float4(0.f, 0.f, 0.f, 0.f);
        float4 wv = *(const float4*)(wptr + (size_t)k0 * HC);
        As[akq + 0][arow] = av.x; As[akq + 1][arow] = av.y;
        As[akq + 2][arow] = av.z; As[akq + 3][arow] = av.w;
        *(float4*)&Ws[wkr][wnq] = wv;
        __syncthreads();
#pragma unroll
        for (int kk = 0; kk < 16; kk++) {
            float a[4], b[4];
            *(float4*)a = *(const float4*)&As[kk][ty * 4];
            *(float4*)b = *(const float4*)&Ws[kk][tx * 4];
#pragma unroll
            for (int i = 0; i < 4; i++)
#pragma unroll
                for (int j = 0; j < 4; j++)
                    acc[i][j] = fmaf(a[i], b[j], acc[i][j]);
        }
        __syncthreads();
    }
#pragma unroll
    for (int i = 0; i < 4; i++) {
        int row = bm + ty * 4 + i;
        if (row < M) {
            float4 o;
            o.x = acc[i][0]; o.y = acc[i][1]; o.z = acc[i][2]; o.w = acc[i][3];
            *(float4*)(C + (size_t)row * HC + bn + tx * 4) = o;
        }
    }
}

// ===================== edge kernels (unchanged from passing R5) ===========
__global__ __launch_bounds__(256) void edge_logits(const float* __restrict__ xl,
                                                   const float* __restrict__ xr,
                                                   const float* __restrict__ RE,
                                                   const int* __restrict__ ei,
                                                   const int* __restrict__ rel,
                                                   const float* __restrict__ att,
                                                   float* __restrict__ logits,
                                                   unsigned* __restrict__ menc) {
    int warp = (blockIdx.x * blockDim.x + threadIdx.x) >> 5;
    int lane = threadIdx.x & 31;
    if (warp >= ETOT) return;
    int s, d, r;
    if (warp < N_EDGES) { s = ei[warp]; d = ei[N_EDGES + warp]; r = rel[warp]; }
    else                { s = d = warp - N_EDGES; r = N_RELS; }
    const float4* pl = (const float4*)(xl + (size_t)s * HC);
    const float4* pr = (const float4*)(xr + (size_t)d * HC);
    const float4* pe = (const float4*)(RE + (size_t)r * HC);
    const float4* pa = (const float4*)att;
    float lg[4];
#pragma unroll
    for (int h = 0; h < 4; h++) {
        int idx = h * 32 + lane;
        float4 a = pl[idx], b = pr[idx], c = pe[idx], t = pa[idx];
        float x0 = a.x + b.x + c.x; x0 = x0 > 0.f ? x0 : NEG_SLOPE * x0;
        float x1 = a.y + b.y + c.y; x1 = x1 > 0.f ? x1 : NEG_SLOPE * x1;
        float x2 = a.z + b.z + c.z; x2 = x2 > 0.f ? x2 : NEG_SLOPE * x2;
        float x3 = a.w + b.w + c.w; x3 = x3 > 0.f ? x3 : NEG_SLOPE * x3;
        float sum = fmaf(x0, t.x, fmaf(x1, t.y, fmaf(x2, t.z, x3 * t.w)));
        lg[h] = wred(sum);
    }
    if (lane == 0) {
        *(float4*)(logits + (size_t)warp * 4) = make_float4(lg[0], lg[1], lg[2], lg[3]);
        atomicMax(&menc[d * 4 + 0], fenc(lg[0]));
        atomicMax(&menc[d * 4 + 1], fenc(lg[1]));
        atomicMax(&menc[d * 4 + 2], fenc(lg[2]));
        atomicMax(&menc[d * 4 + 3], fenc(lg[3]));
    }
}

__global__ void softmax_p(float* __restrict__ logits,
                          const unsigned* __restrict__ menc,
                          float* __restrict__ denom,
                          const int* __restrict__ ei) {
    int i = blockIdx.x * blockDim.x + threadIdx.x;
    if (i >= ETOT * N_HEAD) return;
    int e = i >> 2, h = i & 3;
    int d = (e < N_EDGES) ? ei[N_EDGES + e] : (e - N_EDGES);
    float m = fdec(menc[d * 4 + h]);
    float p = expf(logits[i] - m);
    logits[i] = p;
    atomicAdd(&denom[d * 4 + h], p);
}

__global__ void init_out(float* __restrict__ out, const float* __restrict__ bias) {
    int i = blockIdx.x * blockDim.x + threadIdx.x;
    if (i < N_NODES * F_DIM) out[i] = bias[i & (F_DIM - 1)];
}

__global__ __launch_bounds__(256) void aggregate(const float* __restrict__ xl,
                                                 const float* __restrict__ p,
                                                 const float* __restrict__ denom,
                                                 const int* __restrict__ ei,
                                                 float* __restrict__ out) {
    int warp = (blockIdx.x * blockDim.x + threadIdx.x) >> 5;
    int lane = threadIdx.x & 31;
    if (warp >= ETOT) return;
    int s, d;
    if (warp < N_EDGES) { s = ei[warp]; d = ei[N_EDGES + warp]; }
    else                { s = d = warp - N_EDGES; }
    float4 p4 = *(const float4*)(p + (size_t)warp * 4);
    float4 dn = *(const float4*)(denom + (size_t)d * 4);
    float a0 = 0.25f * p4.x / dn.x;
    float a1 = 0.25f * p4.y / dn.y;
    float a2 = 0.25f * p4.z / dn.z;
    float a3 = 0.25f * p4.w / dn.w;
    const float* base = xl + (size_t)s * HC;
    float4 v0 = ((const float4*)(base      ))[lane];
    float4 v1 = ((const float4*)(base + 128))[lane];
    float4 v2 = ((const float4*)(base + 256))[lane];
    float4 v3 = ((const float4*)(base + 384))[lane];
    float4 acc;
    acc.x = fmaf(a0, v0.x, fmaf(a1, v1.x, fmaf(a2, v2.x, a3 * v3.x)));
    acc.y = fmaf(a0, v0.y, fmaf(a1, v1.y, fmaf(a2, v2.y, a3 * v3.y)));
    acc.z = fmaf(a0, v0.z, fmaf(a1, v1.z, fmaf(a2, v2.z, a3 * v3.z)));
    acc.w = fmaf(a0, v0.w, fmaf(a1, v1.w, fmaf(a2, v2.w, a3 * v3.w)));
    float* op = out + (size_t)d * F_DIM + lane * 4;
    atomicAdd(op + 0, acc.x);
    atomicAdd(op + 1, acc.y);
    atomicAdd(op + 2, acc.z);
    atomicAdd(op + 3, acc.w);
}

__global__ void copy_rel(const float* __restrict__ relations, float* __restrict__ out) {
    int i = blockIdx.x * blockDim.x + threadIdx.x;
    if (i < N_RELS * F_DIM) out[(size_t)N_NODES * F_DIM + i] = relations[i];
}

// ===================== host ===============================================
extern "C" void kernel_launch(void* const* d_in, const int* in_sizes, int n_in,
                              void* d_out, int out_size) {
    (void)in_sizes; (void)n_in; (void)out_size;
    const float* x         = (const float*)d_in[0];
    const int*   ei        = (const int*)  d_in[1];
    const float* relations = (const float*)d_in[2];
    const int*   relidx    = (const int*)  d_in[3];
    const float* Wl        = (const float*)d_in[4];
    const float* bl        = (const float*)d_in[5];
    const float* Wr        = (const float*)d_in[6];
    const float* br        = (const float*)d_in[7];
    const float* We        = (const float*)d_in[8];
    const float* att       = (const float*)d_in[9];
    const float* bias      = (const float*)d_in[10];
    float* out = (float*)d_out;

    float *xl, *xr, *RE, *relext, *logits, *denom, *hA, *hB, *bc;
    unsigned* menc; int* counts;
    __nv_bfloat16 *A3, *W3;
    cudaGetSymbolAddress((void**)&xl, g_xl);
    cudaGetSymbolAddress((void**)&xr, g_xr);
    cudaGetSymbolAddress((void**)&RE, g_RE);
    cudaGetSymbolAddress((void**)&relext, g_relext);
    cudaGetSymbolAddress((void**)&logits, g_logits);
    cudaGetSymbolAddress((void**)&menc, g_menc);
    cudaGetSymbolAddress((void**)&denom, g_denom);
    cudaGetSymbolAddress((void**)&hA, g_hA);
    cudaGetSymbolAddress((void**)&hB, g_hB);
    cudaGetSymbolAddress((void**)&counts, g_counts);
    cudaGetSymbolAddress((void**)&A3, g_A3);
    cudaGetSymbolAddress((void**)&W3, g_W3);
    cudaGetSymbolAddress((void**)&bc, g_bc);

    cudaFuncSetAttribute(gemm_mma, cudaFuncAttributeMaxDynamicSharedMemorySize, SMEM_MMA);

    // prep: relation mean + weight transpose/split
    fill_u32<<<(N_RELS + 255) / 256, 256>>>((unsigned*)counts, 0u, N_RELS);
    count_rels<<<(N_EDGES + 255) / 256, 256>>>(relidx, counts);
    build_relext<<<N_RELS + 1, 128>>>(relations, counts, relext);
    split_W3<<<(4 * 1024 * F_DIM + 255) / 256, 256>>>(Wl, Wr, bl, br, W3, bc);

    dim3 gMMA((N_NODES + BM - 1) / BM, 1024 / BN);   // 157 x 8
    dim3 gR((N_RELS + 1 + 63) / 64, HC / 64);
    int edgeBlocks = (ETOT * 32 + 255) / 256;

    const float* cur = x;
    for (int l = 0; l < 4; l++) {
        float* outb = (l == 3) ? out : ((l & 1) ? hB : hA);
        split_A3<<<(N_NODES * F_DIM + 255) / 256, 256>>>(cur, A3);
        gemm_mma<<<gMMA, 256, SMEM_MMA>>>(A3, W3 + (size_t)l * 1024 * KTOT,
                                          bc + l * 1024, xl, xr, N_NODES);
        gemm_k128<<<gR, 256>>>(relext, We + (size_t)l * F_DIM * HC, (const float*)0, RE, N_RELS + 1);
        fill_u32<<<(N_NODES * N_HEAD + 255) / 256, 256>>>(menc, 0u, N_NODES * N_HEAD);
        fill_u32<<<(N_NODES * N_HEAD + 255) / 256, 256>>>((unsigned*)denom, 0u, N_NODES * N_HEAD);
        edge_logits<<<edgeBlocks, 256>>>(xl, xr, RE, ei, relidx, att + l * N_HEAD * F_DIM,
                                         logits, menc);
        softmax_p<<<(ETOT * N_HEAD + 255) / 256, 256>>>(logits, menc, denom, ei);
        init_out<<<(N_NODES * F_DIM + 255) / 256, 256>>>(outb, bias + l * F_DIM);
        aggregate<<<edgeBlocks, 256>>>(xl, logits, denom, ei, outb);
        cur = outb;
    }
    copy_rel<<<(N_RELS * F_DIM + 255) / 256, 256>>>(relations, out);
}

// round 12
// speedup vs baseline: 1.6766x; 1.0893x over previous
#include <cuda_runtime.h>
#include <cuda_bf16.h>
#include <math.h>
#include <stdint.h>

#define N_NODES 20000
#define N_EDGES 100000
#define N_RELS  1000
#define F_DIM   128
#define N_HEAD  4
#define HC      512            // N_HEAD * F_DIM
#define ETOT    (N_EDGES + N_NODES)
#define NEG_SLOPE 0.2f
#define KTOT    384            // 3-term split contraction length

// ===================== scratch (device globals; allocation-free) ==========
__device__ __align__(16) float    g_xl[(size_t)N_NODES * HC];      // 41 MB
__device__ __align__(16) float    g_xr[(size_t)N_NODES * HC];      // 41 MB
__device__ __align__(16) float    g_RE[(N_RELS + 1) * HC];         // 2 MB
__device__ __align__(16) float    g_relext[(N_RELS + 1) * F_DIM];  // 0.5 MB
__device__ __align__(16) float    g_hA[(size_t)N_NODES * F_DIM];
__device__ __align__(16) float    g_hB[(size_t)N_NODES * F_DIM];
__device__ int g_counts[N_RELS];
// CSR (dst-sorted edges, built once per launch)
__device__ int g_offs[N_NODES + 1];
__device__ int g_cursor[N_NODES];
__device__ int g_esrc[ETOT];
__device__ int g_erel[ETOT];
// bf16 3-term split operands: A3[m][384] = [Ah|Al|Ah], W3[l][n][384] = [Wh|Wh|Wl]
__device__ __align__(16) __nv_bfloat16 g_A3[(size_t)N_NODES * KTOT];    // 15.4 MB
__device__ __align__(16) __nv_bfloat16 g_W3[(size_t)4 * 1024 * KTOT];   // 3.1 MB
__device__ __align__(16) float         g_bc[4 * 1024];                  // combined bias

// ===================== generic helpers ====================================
__device__ __forceinline__ float wred(float v) {
    v += __shfl_xor_sync(0xffffffffu, v, 16);
    v += __shfl_xor_sync(0xffffffffu, v, 8);
    v += __shfl_xor_sync(0xffffffffu, v, 4);
    v += __shfl_xor_sync(0xffffffffu, v, 2);
    v += __shfl_xor_sync(0xffffffffu, v, 1);
    return v;
}
__device__ __forceinline__ uint32_t smem_u32(const void* p) {
    uint32_t a;
    asm("{ .reg .u64 t; cvta.to.shared.u64 t, %1; cvt.u32.u64 %0, t; }" : "=r"(a) : "l"(p));
    return a;
}
__device__ __forceinline__ uint32_t swz(uint32_t b) { return b ^ ((b >> 3) & 0x70u); }

// ===================== small utility kernels ==============================
__global__ void fill_u32(unsigned* p, unsigned v, int n) {
    int i = blockIdx.x * blockDim.x + threadIdx.x;
    if (i < n) p[i] = v;
}
__global__ void count_rels(const int* __restrict__ rel, int* __restrict__ counts) {
    int i = blockIdx.x * blockDim.x + threadIdx.x;
    if (i < N_EDGES) atomicAdd(&counts[rel[i]], 1);
}
__global__ void build_relext(const float* __restrict__ relations,
                             const int* __restrict__ counts,
                             float* __restrict__ relext) {
    int r = blockIdx.x;
    int k = threadIdx.x;   // 128
    if (r < N_RELS) {
        relext[r * F_DIM + k] = relations[r * F_DIM + k];
    } else {
        __shared__ int sc[N_RELS];
        for (int i = k; i < N_RELS; i += 128) sc[i] = counts[i];
        __syncthreads();
        float s = 0.f;
        for (int i = 0; i < N_RELS; i++)
            s = fmaf((float)sc[i], relations[i * F_DIM + k], s);
        relext[r * F_DIM + k] = s * (1.0f / (float)N_EDGES);
    }
}

// ---------------- CSR build ----------------
__global__ void count_deg(const int* __restrict__ ei, int* __restrict__ cnt) {
    int e = blockIdx.x * blockDim.x + threadIdx.x;
    if (e < N_EDGES) atomicAdd(&cnt[ei[N_EDGES + e]], 1);
}
__global__ __launch_bounds__(1024) void scan_offsets(const int* __restrict__ cnt,
                                                     int* __restrict__ offs) {
    __shared__ int part[1024];
    int t = threadIdx.x;
    int base = t * 20;
    int local[20];
    int s = 0;
#pragma unroll
    for (int i = 0; i < 20; i++) {
        int idx = base + i;
        local[i] = s;
        s += (idx < N_NODES) ? cnt[idx] : 0;
    }
    part[t] = s;
    __syncthreads();
    for (int off = 1; off < 1024; off <<= 1) {
        int v = 0;
        if (t >= off) v = part[t - off];
        __syncthreads();
        if (t >= off) part[t] += v;
        __syncthreads();
    }
    int pre = (t > 0) ? part[t - 1] : 0;
#pragma unroll
    for (int i = 0; i < 20; i++) {
        int idx = base + i;
        if (idx < N_NODES) offs[idx] = pre + local[i];
    }
    if (t == 1023) offs[N_NODES] = part[1023];
}
__global__ void copy_off(const int* __restrict__ offs, int* __restrict__ cur) {
    int i = blockIdx.x * blockDim.x + threadIdx.x;
    if (i < N_NODES) cur[i] = offs[i];
}
__global__ void scatter_edges(const int* __restrict__ ei, const int* __restrict__ rel,
                              int* __restrict__ cur, int* __restrict__ esrc,
                              int* __restrict__ erel) {
    int e = blockIdx.x * blockDim.x + threadIdx.x;
    if (e < N_EDGES) {
        int d = ei[N_EDGES + e];
        int pos = atomicAdd(&cur[d], 1);
        esrc[pos] = ei[e];
        erel[pos] = rel[e];
    } else if (e < ETOT) {
        int n = e - N_EDGES;
        int pos = atomicAdd(&cur[n], 1);
        esrc[pos] = n;
        erel[pos] = N_RELS;
    }
}

// A3[m][0:128]=hi, [128:256]=lo, [256:384]=hi
__global__ void split_A3(const float* __restrict__ in, __nv_bfloat16* __restrict__ A3) {
    int i = blockIdx.x * blockDim.x + threadIdx.x;
    if (i >= N_NODES * F_DIM) return;
    int m = i >> 7, k = i & 127;
    float v = in[i];
    __nv_bfloat16 h = __float2bfloat16(v);
    __nv_bfloat16 l = __float2bfloat16(v - __bfloat162float(h));
    __nv_bfloat16* row = A3 + (size_t)m * KTOT;
    row[k] = h; row[128 + k] = l; row[256 + k] = h;
}

// W3[l][n][0:128]=Wh, [128:256]=Wh, [256:384]=Wl ; n<512 from Wl-proj, else Wr-proj
__global__ void split_W3(const float* __restrict__ Wl, const float* __restrict__ Wr,
                         const float* __restrict__ bl, const float* __restrict__ br,
                         __nv_bfloat16* __restrict__ W3, float* __restrict__ bc) {
    int idx = blockIdx.x * blockDim.x + threadIdx.x;
    if (idx < 4 * 1024) {
        int l = idx >> 10, n = idx & 1023;
        bc[idx] = (n < 512) ? bl[l * 512 + n] : br[l * 512 + (n - 512)];
    }
    if (idx >= 4 * 1024 * F_DIM) return;
    int l = idx / (1024 * F_DIM);
    int rem = idx - l * 1024 * F_DIM;
    int n = rem >> 7, k = rem & 127;
    float v = (n < 512) ? Wl[(size_t)l * F_DIM * 512 + (size_t)k * 512 + n]
                        : Wr[(size_t)l * F_DIM * 512 + (size_t)k * 512 + (n - 512)];
    __nv_bfloat16 h = __float2bfloat16(v);
    __nv_bfloat16 lo = __float2bfloat16(v - __bfloat162float(h));
    __nv_bfloat16* row = W3 + ((size_t)l * 1024 + n) * KTOT;
    row[k] = h; row[128 + k] = h; row[256 + k] = lo;
}

// ===================== mma.sync bf16 GEMM (unchanged, passing) ============
#define BM 128
#define BN 128
#define BK 64
#define NCHUNK 6
#define CHUNK_BYTES 16384
#define BUF_BYTES   32768
#define SMEM_MMA    65536

__device__ __forceinline__ void ldsm4(uint32_t& r0, uint32_t& r1, uint32_t& r2,
                                      uint32_t& r3, uint32_t addr) {
    asm volatile("ldmatrix.sync.aligned.m8n8.x4.shared.b16 {%0,%1,%2,%3}, [%4];"
                 : "=r"(r0), "=r"(r1), "=r"(r2), "=r"(r3) : "r"(addr));
}
__device__ __forceinline__ void mma16816(float* c, const uint32_t* a, const uint32_t* b) {
    asm volatile(
        "mma.sync.aligned.m16n8k16.row.col.f32.bf16.bf16.f32 "
        "{%0,%1,%2,%3}, {%4,%5,%6,%7}, {%8,%9}, {%0,%1,%2,%3};"
        : "+f"(c[0]), "+f"(c[1]), "+f"(c[2]), "+f"(c[3])
        : "r"(a[0]), "r"(a[1]), "r"(a[2]), "r"(a[3]), "r"(b[0]), "r"(b[1]));
}

__global__ __launch_bounds__(256, 2) void gemm_mma(
    const __nv_bfloat16* __restrict__ A3, const __nv_bfloat16* __restrict__ W3,
    const float* __restrict__ bc,
    float* __restrict__ xl, float* __restrict__ xr, int Mtot) {
    extern __shared__ char smem[];
    uint32_t sb = smem_u32(smem);
    int tid = threadIdx.x;
    int wid = tid >> 5, lane = tid & 31;
    int bm = blockIdx.x * BM;
    int n0 = blockIdx.y * BN;
    int wm = wid & 1;
    int wn = wid >> 1;

    auto load_chunk = [&](int buf, int k0) {
        uint32_t abase = sb + buf * BUF_BYTES;
        uint32_t bbase = abase + CHUNK_BYTES;
#pragma unroll
        for (int p = 0; p < 4; p++) {
            int unit = tid + p * 256;
            int row = unit >> 3, c16 = unit & 7;
            uint32_t off = swz((uint32_t)(row * 128 + c16 * 16));
            const void* asrc = A3 + (size_t)(bm + row) * KTOT + k0 + c16 * 8;
            int sz = (bm + row < Mtot) ? 16 : 0;
            asm volatile("cp.async.cg.shared.global [%0], [%1], 16, %2;"
                         :: "r"(abase + off), "l"(asrc), "r"(sz) : "memory");
            const void* bsrc = W3 + (size_t)(n0 + row) * KTOT + k0 + c16 * 8;
            asm volatile("cp.async.cg.shared.global [%0], [%1], 16;"
                         :: "r"(bbase + off), "l"(bsrc) : "memory");
        }
        asm volatile("cp.async.commit_group;" ::: "memory");
    };

    uint32_t aSw[4], bSw[2];
#pragma unroll
    for (int mf = 0; mf < 4; mf++) {
        int row = wm * 64 + mf * 16 + (lane & 15);
        aSw[mf] = swz((uint32_t)(row * 128 + ((lane >> 4) << 4)));
    }
#pragma unroll
    for (int nh = 0; nh < 2; nh++) {
        int row = wn * 32 + nh * 16 + (lane & 7) + ((lane & 16) ? 8 : 0);
        bSw[nh] = swz((uint32_t)(row * 128 + ((lane & 8) ? 16 : 0)));
    }

    float acc[4][4][4] = {};

    load_chunk(0, 0);
#pragma unroll
    for (int c = 0; c < NCHUNK; c++) {
        if (c + 1 < NCHUNK) {
            load_chunk((c + 1) & 1, (c + 1) * BK);
            asm volatile("cp.async.wait_group 1;" ::: "memory");
        } else {
            asm volatile("cp.async.wait_group 0;" ::: "memory");
        }
        __syncthreads();
        uint32_t As = sb + (c & 1) * BUF_BYTES;
        uint32_t Bs = As + CHUNK_BYTES;
#pragma unroll
        for (int kk = 0; kk < 4; kk++) {
            uint32_t kx = (uint32_t)kk << 5;
            uint32_t a[4][4], b[4][2];
#pragma unroll
            for (int mf = 0; mf < 4; mf++)
                ldsm4(a[mf][0], a[mf][1], a[mf][2], a[mf][3], As + (aSw[mf] ^ kx));
#pragma unroll
            for (int nh = 0; nh < 2; nh++) {
                uint32_t r0, r1, r2, r3;
                ldsm4(r0, r1, r2, r3, Bs + (bSw[nh] ^ kx));
                b[nh * 2][0] = r0; b[nh * 2][1] = r1;
                b[nh * 2 + 1][0] = r2; b[nh * 2 + 1][1] = r3;
            }
#pragma unroll
            for (int mf = 0; mf < 4; mf++)
#pragma unroll
                for (int nf = 0; nf < 4; nf++)
                    mma16816(acc[mf][nf], a[mf], b[nf]);
        }
        __syncthreads();
    }

    float* outp = (n0 < 512) ? xl : xr;
    int col0 = (n0 < 512) ? n0 : n0 - 512;
#pragma unroll
    for (int mf = 0; mf < 4; mf++) {
        int m0 = bm + wm * 64 + mf * 16 + (lane >> 2);
#pragma unroll
        for (int nf = 0; nf < 4; nf++) {
            int cl = wn * 32 + nf * 8 + (lane & 3) * 2;
            float bx = __ldg(bc + n0 + cl), by = __ldg(bc + n0 + cl + 1);
            if (m0 < Mtot) {
                float2 v = make_float2(acc[mf][nf][0] + bx, acc[mf][nf][1] + by);
                *(float2*)(outp + (size_t)m0 * 512 + col0 + cl) = v;
            }
            if (m0 + 8 < Mtot) {
                float2 v = make_float2(acc[mf][nf][2] + bx, acc[mf][nf][3] + by);
                *(float2*)(outp + (size_t)(m0 + 8) * 512 + col0 + cl) = v;
            }
        }
    }
}

// ===================== fp32 GEMM (small RE matmul) ========================
__global__ __launch_bounds__(256) void gemm_k128(const float* __restrict__ A,
                                                 const float* __restrict__ W,
                                                 const float* __restrict__ bias,
                                                 float* __restrict__ C, int M) {
    __shared__ __align__(16) float As[16][64];
    __shared__ __align__(16) float Ws[16][64];
    int tid = threadIdx.x;
    int bm = blockIdx.x * 64;
    int bn = blockIdx.y * 64;
    int tx = tid & 15, ty = tid >> 4;
    float acc[4][4];
#pragma unroll
    for (int i = 0; i < 4; i++)
#pragma unroll
        for (int j = 0; j < 4; j++) acc[i][j] = 0.f;
    int arow = tid >> 2;
    int akq  = (tid & 3) * 4;
    int wkr  = tid >> 4;
    int wnq  = (tid & 15) * 4;
    const bool avalid = (bm + arow) < M;
    const float* aptr = A + (size_t)(bm + arow) * F_DIM + akq;
    const float* wptr = W + (size_t)wkr * HC + bn + wnq;
    for (int k0 = 0; k0 < 128; k0 += 16) {
        float4 av = avalid ? *(const float4*)(aptr + k0) : make_float4(0.f, 0.f, 0.f, 0.f);
        float4 wv = *(const float4*)(wptr + (size_t)k0 * HC);
        As[akq + 0][arow] = av.x; As[akq + 1][arow] = av.y;
        As[akq + 2][arow] = av.z; As[akq + 3][arow] = av.w;
        *(float4*)&Ws[wkr][wnq] = wv;
        __syncthreads();
#pragma unroll
        for (int kk = 0; kk < 16; kk++) {
            float a[4], b[4];
            *(float4*)a = *(const float4*)&As[kk][ty * 4];
            *(float4*)b = *(const float4*)&Ws[kk][tx * 4];
#pragma unroll
            for (int i = 0; i < 4; i++)
#pragma unroll
                for (int j = 0; j < 4; j++)
                    acc[i][j] = fmaf(a[i], b[j], acc[i][j]);
        }
        __syncthreads();
    }
#pragma unroll
    for (int i = 0; i < 4; i++) {
        int row = bm + ty * 4 + i;
        if (row < M) {
            float4 o;
            o.x = acc[i][0]; o.y = acc[i][1]; o.z = acc[i][2]; o.w = acc[i][3];
            *(float4*)(C + (size_t)row * HC + bn + tx * 4) = o;
        }
    }
}

// ===================== fused GAT edge pass ================================
// One warp per dst node: score all incoming edges, online softmax, aggregate.
__global__ __launch_bounds__(256) void gat_fused(
    const float* __restrict__ xl, const float* __restrict__ xr,
    const float* __restrict__ RE,
    const int* __restrict__ esrc, const int* __restrict__ erel,
    const int* __restrict__ offs,
    const float* __restrict__ att, const float* __restrict__ bias,
    float* __restrict__ out) {
    int node = (blockIdx.x * blockDim.x + threadIdx.x) >> 5;
    int lane = threadIdx.x & 31;
    if (node >= N_NODES) return;
    int beg = offs[node], end = offs[node + 1];

    float4 xr4[4], at4[4];
    const float4* pxr = (const float4*)(xr + (size_t)node * HC);
    const float4* pat = (const float4*)att;
#pragma unroll
    for (int h = 0; h < 4; h++) {
        xr4[h] = pxr[h * 32 + lane];
        at4[h] = pat[h * 32 + lane];
    }

    float m[4], den[4];
    float4 acc[4];
#pragma unroll
    for (int h = 0; h < 4; h++) {
        m[h] = -3.0e38f; den[h] = 0.f;
        acc[h] = make_float4(0.f, 0.f, 0.f, 0.f);
    }

    for (int e = beg; e < end; e++) {
        int s = esrc[e], r = erel[e];
        const float4* pxl = (const float4*)(xl + (size_t)s * HC);
        const float4* pe  = (const float4*)(RE + (size_t)r * HC);
        float4 xl4[4], e4[4];
#pragma unroll
        for (int h = 0; h < 4; h++) { xl4[h] = pxl[h * 32 + lane]; e4[h] = pe[h * 32 + lane]; }

        float lg[4];
#pragma unroll
        for (int h = 0; h < 4; h++) {
            float vx = xl4[h].x + xr4[h].x + e4[h].x; vx = vx > 0.f ? vx : NEG_SLOPE * vx;
            float vy = xl4[h].y + xr4[h].y + e4[h].y; vy = vy > 0.f ? vy : NEG_SLOPE * vy;
            float vz = xl4[h].z + xr4[h].z + e4[h].z; vz = vz > 0.f ? vz : NEG_SLOPE * vz;
            float vw = xl4[h].w + xr4[h].w + e4[h].w; vw = vw > 0.f ? vw : NEG_SLOPE * vw;
            float part = fmaf(vx, at4[h].x, fmaf(vy, at4[h].y, fmaf(vz, at4[h].z, vw * at4[h].w)));
            lg[h] = wred(part);
        }
#pragma unroll
        for (int h = 0; h < 4; h++) {
            float nm = fmaxf(m[h], lg[h]);
            float sc = expf(m[h] - nm);
            float p  = expf(lg[h] - nm);
            den[h] = den[h] * sc + p;
            acc[h].x = fmaf(acc[h].x, sc, p * xl4[h].x);
            acc[h].y = fmaf(acc[h].y, sc, p * xl4[h].y);
            acc[h].z = fmaf(acc[h].z, sc, p * xl4[h].z);
            acc[h].w = fmaf(acc[h].w, sc, p * xl4[h].w);
            m[h] = nm;
        }
    }

    float i0 = 0.25f / den[0], i1 = 0.25f / den[1], i2 = 0.25f / den[2], i3 = 0.25f / den[3];
    float4 b4 = ((const float4*)bias)[lane];
    float4 o;
    o.x = fmaf(acc[0].x, i0, fmaf(acc[1].x, i1, fmaf(acc[2].x, i2, fmaf(acc[3].x, i3, b4.x))));
    o.y = fmaf(acc[0].y, i0, fmaf(acc[1].y, i1, fmaf(acc[2].y, i2, fmaf(acc[3].y, i3, b4.y))));
    o.z = fmaf(acc[0].z, i0, fmaf(acc[1].z, i1, fmaf(acc[2].z, i2, fmaf(acc[3].z, i3, b4.z))));
    o.w = fmaf(acc[0].w, i0, fmaf(acc[1].w, i1, fmaf(acc[2].w, i2, fmaf(acc[3].w, i3, b4.w))));
    ((float4*)(out + (size_t)node * F_DIM))[lane] = o;
}

// ===================== tail: copy relations into output ===================
__global__ void copy_rel(const float* __restrict__ relations, float* __restrict__ out) {
    int i = blockIdx.x * blockDim.x + threadIdx.x;
    if (i < N_RELS * F_DIM) out[(size_t)N_NODES * F_DIM + i] = relations[i];
}

// ===================== host ===============================================
extern "C" void kernel_launch(void* const* d_in, const int* in_sizes, int n_in,
                              void* d_out, int out_size) {
    (void)in_sizes; (void)n_in; (void)out_size;
    const float* x         = (const float*)d_in[0];
    const int*   ei        = (const int*)  d_in[1];
    const float* relations = (const float*)d_in[2];
    const int*   relidx    = (const int*)  d_in[3];
    const float* Wl        = (const float*)d_in[4];
    const float* bl        = (const float*)d_in[5];
    const float* Wr        = (const float*)d_in[6];
    const float* br        = (const float*)d_in[7];
    const float* We        = (const float*)d_in[8];
    const float* att       = (const float*)d_in[9];
    const float* bias      = (const float*)d_in[10];
    float* out = (float*)d_out;

    float *xl, *xr, *RE, *relext, *hA, *hB, *bc;
    int *counts, *offs, *cursor, *esrc, *erel;
    __nv_bfloat16 *A3, *W3;
    cudaGetSymbolAddress((void**)&xl, g_xl);
    cudaGetSymbolAddress((void**)&xr, g_xr);
    cudaGetSymbolAddress((void**)&RE, g_RE);
    cudaGetSymbolAddress((void**)&relext, g_relext);
    cudaGetSymbolAddress((void**)&hA, g_hA);
    cudaGetSymbolAddress((void**)&hB, g_hB);
    cudaGetSymbolAddress((void**)&counts, g_counts);
    cudaGetSymbolAddress((void**)&offs, g_offs);
    cudaGetSymbolAddress((void**)&cursor, g_cursor);
    cudaGetSymbolAddress((void**)&esrc, g_esrc);
    cudaGetSymbolAddress((void**)&erel, g_erel);
    cudaGetSymbolAddress((void**)&A3, g_A3);
    cudaGetSymbolAddress((void**)&W3, g_W3);
    cudaGetSymbolAddress((void**)&bc, g_bc);

    cudaFuncSetAttribute(gemm_mma, cudaFuncAttributeMaxDynamicSharedMemorySize, SMEM_MMA);

    // ---- CSR build (once; graph static within launch). counts init = 1 (self loop).
    fill_u32<<<(N_NODES + 255) / 256, 256>>>((unsigned*)cursor, 1u, N_NODES);
    count_deg<<<(N_EDGES + 255) / 256, 256>>>(ei, cursor);
    scan_offsets<<<1, 1024>>>(cursor, offs);
    copy_off<<<(N_NODES + 255) / 256, 256>>>(offs, cursor);
    scatter_edges<<<(ETOT + 255) / 256, 256>>>(ei, relidx, cursor, esrc, erel);

    // ---- relation mean + weight transpose/split
    fill_u32<<<(N_RELS + 255) / 256, 256>>>((unsigned*)counts, 0u, N_RELS);
    count_rels<<<(N_EDGES + 255) / 256, 256>>>(relidx, counts);
    build_relext<<<N_RELS + 1, 128>>>(relations, counts, relext);
    split_W3<<<(4 * 1024 * F_DIM + 255) / 256, 256>>>(Wl, Wr, bl, br, W3, bc);

    dim3 gMMA((N_NODES + BM - 1) / BM, 1024 / BN);   // 157 x 8
    dim3 gR((N_RELS + 1 + 63) / 64, HC / 64);
    int nodeBlocks = (N_NODES * 32 + 255) / 256;

    const float* cur = x;
    for (int l = 0; l < 4; l++) {
        float* outb = (l == 3) ? out : ((l & 1) ? hB : hA);
        split_A3<<<(N_NODES * F_DIM + 255) / 256, 256>>>(cur, A3);
        gemm_mma<<<gMMA, 256, SMEM_MMA>>>(A3, W3 + (size_t)l * 1024 * KTOT,
                                          bc + l * 1024, xl, xr, N_NODES);
        gemm_k128<<<gR, 256>>>(relext, We + (size_t)l * F_DIM * HC, (const float*)0, RE, N_RELS + 1);
        gat_fused<<<nodeBlocks, 256>>>(xl, xr, RE, esrc, erel, offs,
                                       att + l * N_HEAD * F_DIM, bias + l * F_DIM, outb);
        cur = outb;
    }
    copy_rel<<<(N_RELS * F_DIM + 255) / 256, 256>>>(relations, out);
}

// round 13
// speedup vs baseline: 1.8098x; 1.0795x over previous
#include <cuda_runtime.h>
#include <cuda_bf16.h>
#include <math.h>
#include <stdint.h>

#define N_NODES 20000
#define N_EDGES 100000
#define N_RELS  1000
#define F_DIM   128
#define N_HEAD  4
#define HC      512            // N_HEAD * F_DIM
#define ETOT    (N_EDGES + N_NODES)
#define NEG_SLOPE 0.2f
#define KTOT    384            // 3-term split contraction length

// ===================== scratch (device globals; allocation-free) ==========
__device__ __align__(16) float    g_xl[(size_t)N_NODES * HC];      // 41 MB
__device__ __align__(16) float    g_xr[(size_t)N_NODES * HC];      // 41 MB
__device__ __align__(16) float    g_RE[(N_RELS + 1) * HC];         // 2 MB
__device__ __align__(16) float    g_relext[(N_RELS + 1) * F_DIM];  // 0.5 MB
__device__ int g_counts[N_RELS];
// CSR (dst-sorted edges, built once per launch)
__device__ int  g_offs[N_NODES + 1];
__device__ int  g_cursor[N_NODES];
__device__ int2 g_epk[ETOT];                                        // (src, rel)
// bf16 3-term split operands: A3[m][384] = [Ah|Al|Ah], W3[l][n][384] = [Wh|Wh|Wl]
__device__ __align__(16) __nv_bfloat16 g_A3[(size_t)N_NODES * KTOT];    // 15.4 MB
__device__ __align__(16) __nv_bfloat16 g_W3[(size_t)4 * 1024 * KTOT];   // 3.1 MB
__device__ __align__(16) float         g_bc[4 * 1024];                  // combined bias

// ===================== generic helpers ====================================
__device__ __forceinline__ float wred(float v) {
    v += __shfl_xor_sync(0xffffffffu, v, 16);
    v += __shfl_xor_sync(0xffffffffu, v, 8);
    v += __shfl_xor_sync(0xffffffffu, v, 4);
    v += __shfl_xor_sync(0xffffffffu, v, 2);
    v += __shfl_xor_sync(0xffffffffu, v, 1);
    return v;
}
__device__ __forceinline__ uint32_t smem_u32(const void* p) {
    uint32_t a;
    asm("{ .reg .u64 t; cvta.to.shared.u64 t, %1; cvt.u32.u64 %0, t; }" : "=r"(a) : "l"(p));
    return a;
}
__device__ __forceinline__ uint32_t swz(uint32_t b) { return b ^ ((b >> 3) & 0x70u); }
__device__ __forceinline__ void pfL1(const void* p) {
    asm volatile("prefetch.global.L1 [%0];" :: "l"(p));
}

// ===================== small utility kernels ==============================
__global__ void fill_u32(unsigned* p, unsigned v, int n) {
    int i = blockIdx.x * blockDim.x + threadIdx.x;
    if (i < n) p[i] = v;
}
__global__ void count_rels(const int* __restrict__ rel, int* __restrict__ counts) {
    int i = blockIdx.x * blockDim.x + threadIdx.x;
    if (i < N_EDGES) atomicAdd(&counts[rel[i]], 1);
}
__global__ void build_relext(const float* __restrict__ relations,
                             const int* __restrict__ counts,
                             float* __restrict__ relext) {
    int r = blockIdx.x;
    int k = threadIdx.x;   // 128
    if (r < N_RELS) {
        relext[r * F_DIM + k] = relations[r * F_DIM + k];
    } else {
        __shared__ int sc[N_RELS];
        for (int i = k; i < N_RELS; i += 128) sc[i] = counts[i];
        __syncthreads();
        float s = 0.f;
        for (int i = 0; i < N_RELS; i++)
            s = fmaf((float)sc[i], relations[i * F_DIM + k], s);
        relext[r * F_DIM + k] = s * (1.0f / (float)N_EDGES);
    }
}

// ---------------- CSR build ----------------
__global__ void count_deg(const int* __restrict__ ei, int* __restrict__ cnt) {
    int e = blockIdx.x * blockDim.x + threadIdx.x;
    if (e < N_EDGES) atomicAdd(&cnt[ei[N_EDGES + e]], 1);
}
__global__ __launch_bounds__(1024) void scan_offsets(const int* __restrict__ cnt,
                                                     int* __restrict__ offs,
                                                     int* __restrict__ cur) {
    __shared__ int part[1024];
    int t = threadIdx.x;
    int base = t * 20;
    int local[20];
    int s = 0;
#pragma unroll
    for (int i = 0; i < 20; i++) {
        int idx = base + i;
        local[i] = s;
        s += (idx < N_NODES) ? cnt[idx] : 0;
    }
    part[t] = s;
    __syncthreads();
    for (int off = 1; off < 1024; off <<= 1) {
        int v = 0;
        if (t >= off) v = part[t - off];
        __syncthreads();
        if (t >= off) part[t] += v;
        __syncthreads();
    }
    int pre = (t > 0) ? part[t - 1] : 0;
#pragma unroll
    for (int i = 0; i < 20; i++) {
        int idx = base + i;
        if (idx < N_NODES) { offs[idx] = pre + local[i]; cur[idx] = pre + local[i]; }
    }
    if (t == 1023) offs[N_NODES] = part[1023];
}
__global__ void scatter_edges(const int* __restrict__ ei, const int* __restrict__ rel,
                              int* __restrict__ cur, int2* __restrict__ epk) {
    int e = blockIdx.x * blockDim.x + threadIdx.x;
    if (e < N_EDGES) {
        int d = ei[N_EDGES + e];
        int pos = atomicAdd(&cur[d], 1);
        epk[pos] = make_int2(ei[e], rel[e]);
    } else if (e < ETOT) {
        int n = e - N_EDGES;
        int pos = atomicAdd(&cur[n], 1);
        epk[pos] = make_int2(n, N_RELS);
    }
}

// A3[m][0:128]=hi, [128:256]=lo, [256:384]=hi  (layer-0 input only)
__global__ void split_A3(const float* __restrict__ in, __nv_bfloat16* __restrict__ A3) {
    int i = blockIdx.x * blockDim.x + threadIdx.x;
    if (i >= N_NODES * F_DIM) return;
    int m = i >> 7, k = i & 127;
    float v = in[i];
    __nv_bfloat16 h = __float2bfloat16(v);
    __nv_bfloat16 l = __float2bfloat16(v - __bfloat162float(h));
    __nv_bfloat16* row = A3 + (size_t)m * KTOT;
    row[k] = h; row[128 + k] = l; row[256 + k] = h;
}

// W3[l][n][0:128]=Wh, [128:256]=Wh, [256:384]=Wl ; n<512 from Wl-proj, else Wr-proj
__global__ void split_W3(const float* __restrict__ Wl, const float* __restrict__ Wr,
                         const float* __restrict__ bl, const float* __restrict__ br,
                         __nv_bfloat16* __restrict__ W3, float* __restrict__ bc) {
    int idx = blockIdx.x * blockDim.x + threadIdx.x;
    if (idx < 4 * 1024) {
        int l = idx >> 10, n = idx & 1023;
        bc[idx] = (n < 512) ? bl[l * 512 + n] : br[l * 512 + (n - 512)];
    }
    if (idx >= 4 * 1024 * F_DIM) return;
    int l = idx / (1024 * F_DIM);
    int rem = idx - l * 1024 * F_DIM;
    int n = rem >> 7, k = rem & 127;
    float v = (n < 512) ? Wl[(size_t)l * F_DIM * 512 + (size_t)k * 512 + n]
                        : Wr[(size_t)l * F_DIM * 512 + (size_t)k * 512 + (n - 512)];
    __nv_bfloat16 h = __float2bfloat16(v);
    __nv_bfloat16 lo = __float2bfloat16(v - __bfloat162float(h));
    __nv_bfloat16* row = W3 + ((size_t)l * 1024 + n) * KTOT;
    row[k] = h; row[128 + k] = h; row[256 + k] = lo;
}

// ===================== mma.sync bf16 GEMM (unchanged, passing) ============
#define BM 128
#define BN 128
#define BK 64
#define NCHUNK 6
#define CHUNK_BYTES 16384
#define BUF_BYTES   32768
#define SMEM_MMA    65536

__device__ __forceinline__ void ldsm4(uint32_t& r0, uint32_t& r1, uint32_t& r2,
                                      uint32_t& r3, uint32_t addr) {
    asm volatile("ldmatrix.sync.aligned.m8n8.x4.shared.b16 {%0,%1,%2,%3}, [%4];"
                 : "=r"(r0), "=r"(r1), "=r"(r2), "=r"(r3) : "r"(addr));
}
__device__ __forceinline__ void mma16816(float* c, const uint32_t* a, const uint32_t* b) {
    asm volatile(
        "mma.sync.aligned.m16n8k16.row.col.f32.bf16.bf16.f32 "
        "{%0,%1,%2,%3}, {%4,%5,%6,%7}, {%8,%9}, {%0,%1,%2,%3};"
        : "+f"(c[0]), "+f"(c[1]), "+f"(c[2]), "+f"(c[3])
        : "r"(a[0]), "r"(a[1]), "r"(a[2]), "r"(a[3]), "r"(b[0]), "r"(b[1]));
}

__global__ __launch_bounds__(256, 2) void gemm_mma(
    const __nv_bfloat16* __restrict__ A3, const __nv_bfloat16* __restrict__ W3,
    const float* __restrict__ bc,
    float* __restrict__ xl, float* __restrict__ xr, int Mtot) {
    extern __shared__ char smem[];
    uint32_t sb = smem_u32(smem);
    int tid = threadIdx.x;
    int wid = tid >> 5, lane = tid & 31;
    int bm = blockIdx.x * BM;
    int n0 = blockIdx.y * BN;
    int wm = wid & 1;
    int wn = wid >> 1;

    auto load_chunk = [&](int buf, int k0) {
        uint32_t abase = sb + buf * BUF_BYTES;
        uint32_t bbase = abase + CHUNK_BYTES;
#pragma unroll
        for (int p = 0; p < 4; p++) {
            int unit = tid + p * 256;
            int row = unit >> 3, c16 = unit & 7;
            uint32_t off = swz((uint32_t)(row * 128 + c16 * 16));
            const void* asrc = A3 + (size_t)(bm + row) * KTOT + k0 + c16 * 8;
            int sz = (bm + row < Mtot) ? 16 : 0;
            asm volatile("cp.async.cg.shared.global [%0], [%1], 16, %2;"
                         :: "r"(abase + off), "l"(asrc), "r"(sz) : "memory");
            const void* bsrc = W3 + (size_t)(n0 + row) * KTOT + k0 + c16 * 8;
            asm volatile("cp.async.cg.shared.global [%0], [%1], 16;"
                         :: "r"(bbase + off), "l"(bsrc) : "memory");
        }
        asm volatile("cp.async.commit_group;" ::: "memory");
    };

    uint32_t aSw[4], bSw[2];
#pragma unroll
    for (int mf = 0; mf < 4; mf++) {
        int row = wm * 64 + mf * 16 + (lane & 15);
        aSw[mf] = swz((uint32_t)(row * 128 + ((lane >> 4) << 4)));
    }
#pragma unroll
    for (int nh = 0; nh < 2; nh++) {
        int row = wn * 32 + nh * 16 + (lane & 7) + ((lane & 16) ? 8 : 0);
        bSw[nh] = swz((uint32_t)(row * 128 + ((lane & 8) ? 16 : 0)));
    }

    float acc[4][4][4] = {};

    load_chunk(0, 0);
#pragma unroll
    for (int c = 0; c < NCHUNK; c++) {
        if (c + 1 < NCHUNK) {
            load_chunk((c + 1) & 1, (c + 1) * BK);
            asm volatile("cp.async.wait_group 1;" ::: "memory");
        } else {
            asm volatile("cp.async.wait_group 0;" ::: "memory");
        }
        __syncthreads();
        uint32_t As = sb + (c & 1) * BUF_BYTES;
        uint32_t Bs = As + CHUNK_BYTES;
#pragma unroll
        for (int kk = 0; kk < 4; kk++) {
            uint32_t kx = (uint32_t)kk << 5;
            uint32_t a[4][4], b[4][2];
#pragma unroll
            for (int mf = 0; mf < 4; mf++)
                ldsm4(a[mf][0], a[mf][1], a[mf][2], a[mf][3], As + (aSw[mf] ^ kx));
#pragma unroll
            for (int nh = 0; nh < 2; nh++) {
                uint32_t r0, r1, r2, r3;
                ldsm4(r0, r1, r2, r3, Bs + (bSw[nh] ^ kx));
                b[nh * 2][0] = r0; b[nh * 2][1] = r1;
                b[nh * 2 + 1][0] = r2; b[nh * 2 + 1][1] = r3;
            }
#pragma unroll
            for (int mf = 0; mf < 4; mf++)
#pragma unroll
                for (int nf = 0; nf < 4; nf++)
                    mma16816(acc[mf][nf], a[mf], b[nf]);
        }
        __syncthreads();
    }

    float* outp = (n0 < 512) ? xl : xr;
    int col0 = (n0 < 512) ? n0 : n0 - 512;
#pragma unroll
    for (int mf = 0; mf < 4; mf++) {
        int m0 = bm + wm * 64 + mf * 16 + (lane >> 2);
#pragma unroll
        for (int nf = 0; nf < 4; nf++) {
            int cl = wn * 32 + nf * 8 + (lane & 3) * 2;
            float bx = __ldg(bc + n0 + cl), by = __ldg(bc + n0 + cl + 1);
            if (m0 < Mtot) {
                float2 v = make_float2(acc[mf][nf][0] + bx, acc[mf][nf][1] + by);
                *(float2*)(outp + (size_t)m0 * 512 + col0 + cl) = v;
            }
            if (m0 + 8 < Mtot) {
                float2 v = make_float2(acc[mf][nf][2] + bx, acc[mf][nf][3] + by);
                *(float2*)(outp + (size_t)(m0 + 8) * 512 + col0 + cl) = v;
            }
        }
    }
}

// ===================== fp32 GEMM (small RE matmul) ========================
__global__ __launch_bounds__(256) void gemm_k128(const float* __restrict__ A,
                                                 const float* __restrict__ W,
                                                 const float* __restrict__ bias,
                                                 float* __restrict__ C, int M) {
    __shared__ __align__(16) float As[16][64];
    __shared__ __align__(16) float Ws[16][64];
    int tid = threadIdx.x;
    int bm = blockIdx.x * 64;
    int bn = blockIdx.y * 64;
    int tx = tid & 15, ty = tid >> 4;
    float acc[4][4];
#pragma unroll
    for (int i = 0; i < 4; i++)
#pragma unroll
        for (int j = 0; j < 4; j++) acc[i][j] = 0.f;
    int arow = tid >> 2;
    int akq  = (tid & 3) * 4;
    int wkr  = tid >> 4;
    int wnq  = (tid & 15) * 4;
    const bool avalid = (bm + arow) < M;
    const float* aptr = A + (size_t)(bm + arow) * F_DIM + akq;
    const float* wptr = W + (size_t)wkr * HC + bn + wnq;
    for (int k0 = 0; k0 < 128; k0 += 16) {
        float4 av = avalid ? *(const float4*)(aptr + k0) : make_float4(0.f, 0.f, 0.f, 0.f);
        float4 wv = *(const float4*)(wptr + (size_t)k0 * HC);
        As[akq + 0][arow] = av.x; As[akq + 1][arow] = av.y;
        As[akq + 2][arow] = av.z; As[akq + 3][arow] = av.w;
        *(float4*)&Ws[wkr][wnq] = wv;
        __syncthreads();
#pragma unroll
        for (int kk = 0; kk < 16; kk++) {
            float a[4], b[4];
            *(float4*)a = *(const float4*)&As[kk][ty * 4];
            *(float4*)b = *(const float4*)&Ws[kk][tx * 4];
#pragma unroll
            for (int i = 0; i < 4; i++)
#pragma unroll
                for (int j = 0; j < 4; j++)
                    acc[i][j] = fmaf(a[i], b[j], acc[i][j]);
        }
        __syncthreads();
    }
#pragma unroll
    for (int i = 0; i < 4; i++) {
        int row = bm + ty * 4 + i;
        if (row < M) {
            float4 o;
            o.x = acc[i][0]; o.y = acc[i][1]; o.z = acc[i][2]; o.w = acc[i][3];
            *(float4*)(C + (size_t)row * HC + bn + tx * 4) = o;
        }
    }
}

// ===================== fused GAT edge pass ================================
// One warp per dst node: score all incoming edges, online softmax, aggregate.
// L1 prefetch of the next edge's xl/RE rows hides the gather latency.
// Writes either float out (last layer) or bf16-split A3 (intermediate layers).
__global__ __launch_bounds__(256) void gat_fused(
    const float* __restrict__ xl, const float* __restrict__ xr,
    const float* __restrict__ RE,
    const int2* __restrict__ epk, const int* __restrict__ offs,
    const float* __restrict__ att, const float* __restrict__ bias,
    float* __restrict__ out, __nv_bfloat16* __restrict__ a3) {
    int node = (blockIdx.x * blockDim.x + threadIdx.x) >> 5;
    int lane = threadIdx.x & 31;
    if (node >= N_NODES) return;
    int beg = offs[node], end = offs[node + 1];

    float4 xr4[4], at4[4];
    const float4* pxr = (const float4*)(xr + (size_t)node * HC);
    const float4* pat = (const float4*)att;
#pragma unroll
    for (int h = 0; h < 4; h++) {
        xr4[h] = pxr[h * 32 + lane];
        at4[h] = pat[h * 32 + lane];
    }

    float m[4], den[4];
    float4 acc[4];
#pragma unroll
    for (int h = 0; h < 4; h++) {
        m[h] = -3.0e38f; den[h] = 0.f;
        acc[h] = make_float4(0.f, 0.f, 0.f, 0.f);
    }

    int2 pk = epk[beg];
    // prefetch first edge's rows
    {
        const char* bx = (const char*)(xl + (size_t)pk.x * HC);
        const char* be = (const char*)(RE + (size_t)pk.y * HC);
#pragma unroll
        for (int h = 0; h < 4; h++) {
            pfL1(bx + (h * 32 + lane) * 16);
            pfL1(be + (h * 32 + lane) * 16);
        }
    }

    for (int e = beg; e < end; e++) {
        int s = pk.x, r = pk.y;
        const float4* pxl = (const float4*)(xl + (size_t)s * HC);
        const float4* pe  = (const float4*)(RE + (size_t)r * HC);
        float4 xl4[4], e4[4];
#pragma unroll
        for (int h = 0; h < 4; h++) { xl4[h] = pxl[h * 32 + lane]; e4[h] = pe[h * 32 + lane]; }

        // fetch next indices + prefetch next rows while current loads land
        if (e + 1 < end) {
            pk = epk[e + 1];
            const char* bx = (const char*)(xl + (size_t)pk.x * HC);
            const char* be = (const char*)(RE + (size_t)pk.y * HC);
#pragma unroll
            for (int h = 0; h < 4; h++) {
                pfL1(bx + (h * 32 + lane) * 16);
                pfL1(be + (h * 32 + lane) * 16);
            }
        }

        float lg[4];
#pragma unroll
        for (int h = 0; h < 4; h++) {
            float vx = xl4[h].x + xr4[h].x + e4[h].x; vx = vx > 0.f ? vx : NEG_SLOPE * vx;
            float vy = xl4[h].y + xr4[h].y + e4[h].y; vy = vy > 0.f ? vy : NEG_SLOPE * vy;
            float vz = xl4[h].z + xr4[h].z + e4[h].z; vz = vz > 0.f ? vz : NEG_SLOPE * vz;
            float vw = xl4[h].w + xr4[h].w + e4[h].w; vw = vw > 0.f ? vw : NEG_SLOPE * vw;
            float part = fmaf(vx, at4[h].x, fmaf(vy, at4[h].y, fmaf(vz, at4[h].z, vw * at4[h].w)));
            lg[h] = wred(part);
        }
#pragma unroll
        for (int h = 0; h < 4; h++) {
            float nm = fmaxf(m[h], lg[h]);
            float sc = __expf(m[h] - nm);
            float p  = __expf(lg[h] - nm);
            den[h] = den[h] * sc + p;
            acc[h].x = fmaf(acc[h].x, sc, p * xl4[h].x);
            acc[h].y = fmaf(acc[h].y, sc, p * xl4[h].y);
            acc[h].z = fmaf(acc[h].z, sc, p * xl4[h].z);
            acc[h].w = fmaf(acc[h].w, sc, p * xl4[h].w);
            m[h] = nm;
        }
    }

    float i0 = 0.25f / den[0], i1 = 0.25f / den[1], i2 = 0.25f / den[2], i3 = 0.25f / den[3];
    float4 b4 = ((const float4*)bias)[lane];
    float4 o;
    o.x = fmaf(acc[0].x, i0, fmaf(acc[1].x, i1, fmaf(acc[2].x, i2, fmaf(acc[3].x, i3, b4.x))));
    o.y = fmaf(acc[0].y, i0, fmaf(acc[1].y, i1, fmaf(acc[2].y, i2, fmaf(acc[3].y, i3, b4.y))));
    o.z = fmaf(acc[0].z, i0, fmaf(acc[1].z, i1, fmaf(acc[2].z, i2, fmaf(acc[3].z, i3, b4.z))));
    o.w = fmaf(acc[0].w, i0, fmaf(acc[1].w, i1, fmaf(acc[2].w, i2, fmaf(acc[3].w, i3, b4.w))));

    if (out) {
        ((float4*)(out + (size_t)node * F_DIM))[lane] = o;
    }
    if (a3) {
        // bf16 split: hi at k, lo at 128+k, hi again at 256+k
        float of[4] = {o.x, o.y, o.z, o.w};
        __nv_bfloat16 h[4], lo[4];
#pragma unroll
        for (int j = 0; j < 4; j++) {
            h[j] = __float2bfloat16(of[j]);
            lo[j] = __float2bfloat16(of[j] - __bfloat162float(h[j]));
        }
        __nv_bfloat16* row = a3 + (size_t)node * KTOT + lane * 4;
        *(__nv_bfloat162*)(row)       = *(__nv_bfloat162*)&h[0];
        *(__nv_bfloat162*)(row + 2)   = *(__nv_bfloat162*)&h[2];
        *(__nv_bfloat162*)(row + 128) = *(__nv_bfloat162*)&lo[0];
        *(__nv_bfloat162*)(row + 130) = *(__nv_bfloat162*)&lo[2];
        *(__nv_bfloat162*)(row + 256) = *(__nv_bfloat162*)&h[0];
        *(__nv_bfloat162*)(row + 258) = *(__nv_bfloat162*)&h[2];
    }
}

// ===================== tail: copy relations into output ===================
__global__ void copy_rel(const float* __restrict__ relations, float* __restrict__ out) {
    int i = blockIdx.x * blockDim.x + threadIdx.x;
    if (i < N_RELS * F_DIM) out[(size_t)N_NODES * F_DIM + i] = relations[i];
}

// ===================== host ===============================================
extern "C" void kernel_launch(void* const* d_in, const int* in_sizes, int n_in,
                              void* d_out, int out_size) {
    (void)in_sizes; (void)n_in; (void)out_size;
    const float* x         = (const float*)d_in[0];
    const int*   ei        = (const int*)  d_in[1];
    const float* relations = (const float*)d_in[2];
    const int*   relidx    = (const int*)  d_in[3];
    const float* Wl        = (const float*)d_in[4];
    const float* bl        = (const float*)d_in[5];
    const float* Wr        = (const float*)d_in[6];
    const float* br        = (const float*)d_in[7];
    const float* We        = (const float*)d_in[8];
    const float* att       = (const float*)d_in[9];
    const float* bias      = (const float*)d_in[10];
    float* out = (float*)d_out;

    float *xl, *xr, *RE, *relext, *bc;
    int *counts, *offs, *cursor;
    int2* epk;
    __nv_bfloat16 *A3, *W3;
    cudaGetSymbolAddress((void**)&xl, g_xl);
    cudaGetSymbolAddress((void**)&xr, g_xr);
    cudaGetSymbolAddress((void**)&RE, g_RE);
    cudaGetSymbolAddress((void**)&relext, g_relext);
    cudaGetSymbolAddress((void**)&counts, g_counts);
    cudaGetSymbolAddress((void**)&offs, g_offs);
    cudaGetSymbolAddress((void**)&cursor, g_cursor);
    cudaGetSymbolAddress((void**)&epk, g_epk);
    cudaGetSymbolAddress((void**)&A3, g_A3);
    cudaGetSymbolAddress((void**)&W3, g_W3);
    cudaGetSymbolAddress((void**)&bc, g_bc);

    cudaFuncSetAttribute(gemm_mma, cudaFuncAttributeMaxDynamicSharedMemorySize, SMEM_MMA);

    // ---- CSR build (once; graph static within launch). counts init = 1 (self loop).
    fill_u32<<<(N_NODES + 255) / 256, 256>>>((unsigned*)cursor, 1u, N_NODES);
    count_deg<<<(N_EDGES + 255) / 256, 256>>>(ei, cursor);
    scan_offsets<<<1, 1024>>>(cursor, offs, cursor);
    scatter_edges<<<(ETOT + 255) / 256, 256>>>(ei, relidx, cursor, epk);

    // ---- relation mean + weight transpose/split
    fill_u32<<<(N_RELS + 255) / 256, 256>>>((unsigned*)counts, 0u, N_RELS);
    count_rels<<<(N_EDGES + 255) / 256, 256>>>(relidx, counts);
    build_relext<<<N_RELS + 1, 128>>>(relations, counts, relext);
    split_W3<<<(4 * 1024 * F_DIM + 255) / 256, 256>>>(Wl, Wr, bl, br, W3, bc);

    // layer-0 operand split from x
    split_A3<<<(N_NODES * F_DIM + 255) / 256, 256>>>(x, A3);

    dim3 gMMA((N_NODES + BM - 1) / BM, 1024 / BN);   // 157 x 8
    dim3 gR((N_RELS + 1 + 63) / 64, HC / 64);
    int nodeBlocks = (N_NODES * 32 + 255) / 256;

    for (int l = 0; l < 4; l++) {
        gemm_mma<<<gMMA, 256, SMEM_MMA>>>(A3, W3 + (size_t)l * 1024 * KTOT,
                                          bc + l * 1024, xl, xr, N_NODES);
        gemm_k128<<<gR, 256>>>(relext, We + (size_t)l * F_DIM * HC, (const float*)0, RE, N_RELS + 1);
        gat_fused<<<nodeBlocks, 256>>>(xl, xr, RE, epk, offs,
                                       att + l * N_HEAD * F_DIM, bias + l * F_DIM,
                                       (l == 3) ? out : (float*)0,
                                       (l < 3) ? A3 : (__nv_bfloat16*)0);
    }
    copy_rel<<<(N_RELS * F_DIM + 255) / 256, 256>>>(relations, out);
}